// round 11
// baseline (speedup 1.0000x reference)
#include <cuda_runtime.h>
#include <cuda_bf16.h>
#include <math.h>
#include <stdint.h>

#define NN 10000
#define EE 160000
#define EP 170000          // edges + self loops
#define BB 16
#define F1 1024            // 8 heads * 128
#define F2 512             // 8 heads * 64

// ---------------- scratch (static device globals; no runtime alloc) ----------
__device__ float d_h1 [(size_t)NN * F1];   // x @ W1 (fp32)
__device__ float d_h2 [(size_t)NN * F2];   // h1o @ W2 (fp32)
__device__ float d_h2o[(size_t)NN * F2];   // elu(conv2 out)
__device__ __nv_bfloat16 d_xh[(size_t)NN * 128];
__device__ __nv_bfloat16 d_xl[(size_t)NN * 128];
__device__ __nv_bfloat16 d_h1oh[(size_t)NN * F1];
__device__ __nv_bfloat16 d_h1ol[(size_t)NN * F1];
__device__ __nv_bfloat16 d_w1th[(size_t)F1 * 128];   // W1^T hi  [N=1024, K=128]
__device__ __nv_bfloat16 d_w1tl[(size_t)F1 * 128];
__device__ __nv_bfloat16 d_w2th[(size_t)F2 * F1];    // W2^T hi  [N=512, K=1024]
__device__ __nv_bfloat16 d_w2tl[(size_t)F2 * F1];
__device__ float d_ws1[128 * 16];          // W1 @ [a_src | a_dst]  (conv1 logits)
__device__ float d_asrc[NN * 8];
__device__ float d_adst[NN * 8];
__device__ float d_alpha[(size_t)EP * 8];  // unnormalized exp
__device__ float d_deninv[NN * 8];
__device__ int   d_src[EP];
__device__ int   d_dst[EP];
__device__ int   d_batchi[NN];
__device__ int   d_is64;
__device__ int   d_cnt[NN];
__device__ int   d_rowptr[NN + 1];
__device__ int   d_cursor[NN];
__device__ int   d_eid[EP];
__device__ int   d_bcnt[BB];
__device__ int   d_boff[BB + 1];
__device__ float d_g[BB * F2];

__device__ __forceinline__ float eluf(float x) { return x > 0.0f ? x : expm1f(x); }

// ---------------- dtype probe ------------------------------------------------
__global__ void k_detect(const int* __restrict__ ei_raw) {
    int orv = 0;
#pragma unroll
    for (int i = 1; i < 16; i += 2) orv |= ei_raw[i];
    d_is64 = (orv == 0) ? 1 : 0;
}

__global__ void k_zero() {
    int t = blockIdx.x * blockDim.x + threadIdx.x;
    if (t < NN) d_cnt[t] = 0;
    if (t < BB) d_bcnt[t] = 0;
}

// fused: index normalization + histogram
__global__ void k_convhist(const int* __restrict__ ei_raw,
                           const int* __restrict__ batch_raw) {
    int t = blockIdx.x * blockDim.x + threadIdx.x;
    int is64 = d_is64;
    if (t < EE) {
        int s = is64 ? ei_raw[2 * t]        : ei_raw[t];
        int d = is64 ? ei_raw[2 * (EE + t)] : ei_raw[EE + t];
        d_src[t] = s; d_dst[t] = d;
        atomicAdd(&d_cnt[d], 1);
    } else if (t < EP) {
        d_src[t] = t - EE; d_dst[t] = t - EE;
        atomicAdd(&d_cnt[t - EE], 1);
    }
    if (t < NN) {
        int b = is64 ? batch_raw[2 * t] : batch_raw[t];
        d_batchi[t] = b;
        atomicAdd(&d_bcnt[b], 1);
    }
}

// warp-shuffle scan: 1024 threads, 10 elems/thread, 2 barriers
__global__ void k_scan() {
    __shared__ int wsum[32], wpre[32];
    int t = threadIdx.x, lane = t & 31, w = t >> 5;
    int loc[10];
    int sum = 0;
#pragma unroll
    for (int j = 0; j < 10; j++) {
        int idx = t * 10 + j;
        int v = (idx < NN) ? d_cnt[idx] : 0;
        loc[j] = sum; sum += v;
    }
    int inc = sum;
#pragma unroll
    for (int off = 1; off < 32; off <<= 1) {
        int v = __shfl_up_sync(0xffffffff, inc, off);
        if (lane >= off) inc += v;
    }
    if (lane == 31) wsum[w] = inc;
    __syncthreads();
    if (w == 0) {
        int v = wsum[lane], iv = v;
#pragma unroll
        for (int off = 1; off < 32; off <<= 1) {
            int u = __shfl_up_sync(0xffffffff, iv, off);
            if (lane >= off) iv += u;
        }
        wpre[lane] = iv - v;
    }
    __syncthreads();
    int pre = wpre[w] + inc - sum;   // exclusive prefix for this thread
#pragma unroll
    for (int j = 0; j < 10; j++) {
        int idx = t * 10 + j;
        if (idx < NN) { d_rowptr[idx] = pre + loc[j]; d_cursor[idx] = pre + loc[j]; }
    }
    if (t == 1023) d_rowptr[NN] = pre + sum;
    if (t == 0) {
        d_boff[0] = 0;
        for (int b = 0; b < BB; b++) d_boff[b + 1] = d_boff[b] + d_bcnt[b];
    }
}

__global__ void k_fill() {
    int t = blockIdx.x * blockDim.x + threadIdx.x;
    if (t >= EP) return;
    int pos = atomicAdd(&d_cursor[d_dst[t]], 1);
    d_eid[pos] = t;
}

// ---------------- bf16 hi/lo split kernels ----------------------------------
__global__ void k_split(const float* __restrict__ a,
                        __nv_bfloat16* __restrict__ hi,
                        __nv_bfloat16* __restrict__ lo, int n) {
    int t = blockIdx.x * blockDim.x + threadIdx.x;
    if (t >= n) return;
    float v = a[t];
    __nv_bfloat16 h = __float2bfloat16(v);
    hi[t] = h;
    lo[t] = __float2bfloat16(v - __bfloat162float(h));
}

// W[K,N] -> W^T hi/lo [N,K]
__global__ void k_wsplit(const float* __restrict__ W,
                         __nv_bfloat16* __restrict__ hi,
                         __nv_bfloat16* __restrict__ lo, int K, int N) {
    int t = blockIdx.x * blockDim.x + threadIdx.x;
    if (t >= K * N) return;
    int k = t / N, n = t % N;
    float v = W[t];
    __nv_bfloat16 h = __float2bfloat16(v);
    hi[(size_t)n * K + k] = h;
    lo[(size_t)n * K + k] = __float2bfloat16(v - __bfloat162float(h));
}

// ---------------- ws1 = per-head W1 @ a_src / a_dst  -> [128, 16] ------------
__global__ void k_wvec(const float* __restrict__ W1,
                       const float* __restrict__ as1,
                       const float* __restrict__ ad1) {
    int t = blockIdx.x * blockDim.x + threadIdx.x;
    if (t >= 128 * 16) return;
    int k = t >> 4, h8 = t & 15;
    int h = h8 & 7;
    const float* a = ((h8 < 8) ? as1 : ad1) + h * 128;
    const float* w = W1 + (size_t)k * F1 + h * 128;
    float s = 0.f;
#pragma unroll 8
    for (int c = 0; c < 128; c++) s = fmaf(w[c], a[c], s);
    d_ws1[t] = s;
}

// ---------------- conv1 attention logits from x (uses associativity) --------
__global__ __launch_bounds__(256) void k_attn1x(const float* __restrict__ x) {
    __shared__ float ws[128 * 17];
    int t = threadIdx.x, lane = t & 31, w = t >> 5;
    for (int v = t; v < 2048; v += 256) {
        ws[(v >> 4) * 17 + (v & 15)] = d_ws1[v];
    }
    __syncthreads();
    int i = blockIdx.x * 8 + w;
    float4 xv = ((const float4*)(x + (size_t)i * 128))[lane];
    float acc[16];
#pragma unroll
    for (int h = 0; h < 16; h++) acc[h] = 0.f;
#pragma unroll
    for (int q = 0; q < 4; q++) {
        float xq = (&xv.x)[q];
        const float* wr = &ws[(4 * lane + q) * 17];
#pragma unroll
        for (int h = 0; h < 16; h++) acc[h] = fmaf(xq, wr[h], acc[h]);
    }
#pragma unroll
    for (int off = 16; off > 0; off >>= 1)
#pragma unroll
        for (int h = 0; h < 16; h++)
            acc[h] += __shfl_xor_sync(0xffffffff, acc[h], off);
    if (lane == 0) {
#pragma unroll
        for (int h = 0; h < 8; h++) {
            d_asrc[i * 8 + h] = acc[h];
            d_adst[i * 8 + h] = acc[8 + h];
        }
    }
}

// ================= cp.async 3-stage bf16 3-term GEMM ========================
// C[M,Ntot] = A @ Bt^T.  A hi/lo: [M,K] row-major; Bt hi/lo: [Ntot,K] row-major.
// CTA tile 128x64, BK=32, 256 threads (8 warps, warp tile 32x32), 3 stages.
#define STG    30720
#define ROWB   80                 // 32 halves + 8 pad = 80B rows
#define GSMEM  (3 * STG)

__device__ __forceinline__ void cpa16(uint32_t dst, const void* src, int sz) {
    asm volatile("cp.async.cg.shared.global [%0], [%1], 16, %2;"
                 :: "r"(dst), "l"(src), "r"(sz) : "memory");
}
__device__ __forceinline__ void cpa_commit() {
    asm volatile("cp.async.commit_group;" ::: "memory");
}
template <int N>
__device__ __forceinline__ void cpa_wait() {
    asm volatile("cp.async.wait_group %0;" :: "n"(N) : "memory");
}

__device__ __forceinline__ void ldsm_x4(uint32_t& r0, uint32_t& r1,
                                        uint32_t& r2, uint32_t& r3, uint32_t a) {
    asm volatile("ldmatrix.sync.aligned.m8n8.x4.shared.b16 {%0,%1,%2,%3}, [%4];"
                 : "=r"(r0), "=r"(r1), "=r"(r2), "=r"(r3) : "r"(a));
}

__device__ __forceinline__ void mma16816(float* c, const uint32_t* a,
                                         uint32_t b0, uint32_t b1) {
    asm volatile(
        "mma.sync.aligned.m16n8k16.row.col.f32.bf16.bf16.f32 "
        "{%0,%1,%2,%3}, {%4,%5,%6,%7}, {%8,%9}, {%0,%1,%2,%3};"
        : "+f"(c[0]), "+f"(c[1]), "+f"(c[2]), "+f"(c[3])
        : "r"(a[0]), "r"(a[1]), "r"(a[2]), "r"(a[3]), "r"(b0), "r"(b1));
}

__global__ __launch_bounds__(256) void k_gemm_mma(
    const __nv_bfloat16* __restrict__ Ah, const __nv_bfloat16* __restrict__ Al,
    const __nv_bfloat16* __restrict__ Bh, const __nv_bfloat16* __restrict__ Bl,
    float* __restrict__ C, int M, int Ntot, int K) {
    extern __shared__ char gsm[];
    uint32_t ub = (uint32_t)__cvta_generic_to_shared(gsm);
    int t = threadIdx.x, wid = t >> 5, lane = t & 31;
    int bm = blockIdx.y * 128, bn = blockIdx.x * 64;
    int wm = (wid & 3) * 32;
    int wn = (wid >> 2) * 32;

    float acc[2][4][4];
#pragma unroll
    for (int i = 0; i < 2; i++)
#pragma unroll
        for (int j = 0; j < 4; j++)
#pragma unroll
            for (int q = 0; q < 4; q++) acc[i][j][q] = 0.f;

    int g = lane >> 3, l = lane & 7;
    int arow = wm + (g & 1) * 8 + l;
    int akoff = (g >> 1) * 16;
    int brow = wn + (g >> 1) * 8 + l;
    int bkoff = (g & 1) * 16;

    int NC = K >> 5;

    int ar0 = t >> 2,         ac0 = t & 3;
    int ar1 = (t + 256) >> 2, ac1 = (t + 256) & 3;
    int br = t >> 2, bc = t & 3;

#define ISSUE(cidx, st) do {                                                  \
        uint32_t base = ub + (uint32_t)(st) * STG;                            \
        int k0 = (cidx) << 5;                                                 \
        {   int gr = bm + ar0;                                                \
            size_t gi = (((size_t)gr * K + k0) >> 3) + ac0;                   \
            int ok = (gr < M) ? 16 : 0;                                       \
            cpa16(base + ar0 * ROWB + ac0 * 16, (const uint4*)Ah + gi, ok);   \
            cpa16(base + 10240 + ar0 * ROWB + ac0 * 16, (const uint4*)Al + gi, ok); } \
        {   int gr = bm + ar1;                                                \
            size_t gi = (((size_t)gr * K + k0) >> 3) + ac1;                   \
            int ok = (gr < M) ? 16 : 0;                                       \
            cpa16(base + ar1 * ROWB + ac1 * 16, (const uint4*)Ah + gi, ok);   \
            cpa16(base + 10240 + ar1 * ROWB + ac1 * 16, (const uint4*)Al + gi, ok); } \
        {   size_t gi = (((size_t)(bn + br) * K + k0) >> 3) + bc;             \
            cpa16(base + 20480 + br * ROWB + bc * 16, (const uint4*)Bh + gi, 16); \
            cpa16(base + 25600 + br * ROWB + bc * 16, (const uint4*)Bl + gi, 16); } \
    } while (0)

    ISSUE(0, 0);
    cpa_commit();
    if (NC > 1) ISSUE(1, 1);
    cpa_commit();

    for (int c = 0; c < NC; c++) {
        cpa_wait<1>();
        __syncthreads();
        if (c + 2 < NC) ISSUE(c + 2, (c + 2) % 3);
        cpa_commit();

        uint32_t bA_h = ub + (uint32_t)(c % 3) * STG;
        uint32_t bA_l = bA_h + 10240;
        uint32_t bB_h = bA_h + 20480;
        uint32_t bB_l = bA_h + 25600;

#pragma unroll
        for (int ks = 0; ks < 2; ks++) {
            uint32_t ah[2][4], al[2][4], bh[2][4], bl[2][4];
#pragma unroll
            for (int mt = 0; mt < 2; mt++) {
                uint32_t off = (uint32_t)((arow + mt * 16) * ROWB + ks * 32 + akoff);
                ldsm_x4(ah[mt][0], ah[mt][1], ah[mt][2], ah[mt][3], bA_h + off);
                ldsm_x4(al[mt][0], al[mt][1], al[mt][2], al[mt][3], bA_l + off);
            }
#pragma unroll
            for (int p = 0; p < 2; p++) {
                uint32_t off = (uint32_t)((brow + p * 16) * ROWB + ks * 32 + bkoff);
                ldsm_x4(bh[p][0], bh[p][1], bh[p][2], bh[p][3], bB_h + off);
                ldsm_x4(bl[p][0], bl[p][1], bl[p][2], bl[p][3], bB_l + off);
            }
#pragma unroll
            for (int mt = 0; mt < 2; mt++)
#pragma unroll
                for (int nt = 0; nt < 4; nt++) {
                    int p = nt >> 1, q = (nt & 1) * 2;
                    mma16816(acc[mt][nt], ah[mt], bh[p][q], bh[p][q + 1]);
                    mma16816(acc[mt][nt], al[mt], bh[p][q], bh[p][q + 1]);
                    mma16816(acc[mt][nt], ah[mt], bl[p][q], bl[p][q + 1]);
                }
        }
    }

    int erow = lane >> 2, ecol = (lane & 3) * 2;
#pragma unroll
    for (int mt = 0; mt < 2; mt++)
#pragma unroll
        for (int nt = 0; nt < 4; nt++) {
            int r0 = bm + wm + mt * 16 + erow;
            int cc = bn + wn + nt * 8 + ecol;
            if (r0 < M)
                *(float2*)&C[(size_t)r0 * Ntot + cc] =
                    make_float2(acc[mt][nt][0], acc[mt][nt][1]);
            int r1 = r0 + 8;
            if (r1 < M)
                *(float2*)&C[(size_t)r1 * Ntot + cc] =
                    make_float2(acc[mt][nt][2], acc[mt][nt][3]);
        }
#undef ISSUE
}

// ---------------- conv2 attention coefficients (reads h2) -------------------
template <int C>
__global__ void k_attn(const float* __restrict__ h,
                       const float* __restrict__ a_s,
                       const float* __restrict__ a_d) {
    int i = blockIdx.x;
    int w = threadIdx.x >> 5, l = threadIdx.x & 31;
    const float* hr = h + (size_t)i * 8 * C + w * C;
    float s1 = 0.f, s2 = 0.f;
    for (int c = l; c < C; c += 32) {
        float v = hr[c];
        s1 = fmaf(v, a_s[w * C + c], s1);
        s2 = fmaf(v, a_d[w * C + c], s2);
    }
#pragma unroll
    for (int off = 16; off > 0; off >>= 1) {
        s1 += __shfl_xor_sync(0xffffffff, s1, off);
        s2 += __shfl_xor_sync(0xffffffff, s2, off);
    }
    if (l == 0) { d_asrc[i * 8 + w] = s1; d_adst[i * 8 + w] = s2; }
}

// -------- single-pass segment softmax (no max shift; e bounded ~|8|) --------
__global__ void k_softmax() {
    int t = blockIdx.x * blockDim.x + threadIdx.x;
    if (t >= NN * 8) return;
    int i = t >> 3, h = t & 7;
    int beg = d_rowptr[i], end = d_rowptr[i + 1];
    float ad = d_adst[i * 8 + h];
    float den = 0.f;
    for (int j = beg; j < end; j++) {
        int e = d_eid[j];
        int s = d_src[e];
        float v = d_asrc[s * 8 + h] + ad;
        v = (v > 0.f) ? v : 0.2f * v;          // leaky_relu(0.2)
        float ex = __expf(v);
        d_alpha[(size_t)e * 8 + h] = ex;
        den += ex;
    }
    d_deninv[i * 8 + h] = 1.0f / den;
}

// -------- conv1 aggregation: block per dst node, fused bf16 split out -------
__global__ void k_aggr1(const float* __restrict__ h,
                        const float* __restrict__ bias,
                        __nv_bfloat16* __restrict__ oh,
                        __nv_bfloat16* __restrict__ ol) {
    constexpr int F = F1;
    constexpr int T = F / 4;          // 256 threads
    int i = blockIdx.x, t = threadIdx.x;
    int beg = d_rowptr[i], end = d_rowptr[i + 1];
    int f0 = t, f1 = t + T, f2 = t + 2 * T, f3 = t + 3 * T;
    int h0 = f0 >> 7, h1 = f1 >> 7, h2 = f2 >> 7, h3 = f3 >> 7;
    float a0 = 0.f, a1 = 0.f, a2 = 0.f, a3 = 0.f;
    for (int j = beg; j < end; j++) {
        int e = d_eid[j];
        int s = d_src[e];
        const float* hr = h + (size_t)s * F;
        const float* al = &d_alpha[(size_t)e * 8];
        a0 = fmaf(al[h0], hr[f0], a0);
        a1 = fmaf(al[h1], hr[f1], a1);
        a2 = fmaf(al[h2], hr[f2], a2);
        a3 = fmaf(al[h3], hr[f3], a3);
    }
    const float* iv = &d_deninv[i * 8];
    float v0 = eluf(a0 * iv[h0] + bias[f0]);
    float v1 = eluf(a1 * iv[h1] + bias[f1]);
    float v2 = eluf(a2 * iv[h2] + bias[f2]);
    float v3 = eluf(a3 * iv[h3] + bias[f3]);
    size_t base = (size_t)i * F;
    __nv_bfloat16 b0 = __float2bfloat16(v0), b1h = __float2bfloat16(v1);
    __nv_bfloat16 b2h = __float2bfloat16(v2), b3h = __float2bfloat16(v3);
    oh[base + f0] = b0;  ol[base + f0] = __float2bfloat16(v0 - __bfloat162float(b0));
    oh[base + f1] = b1h; ol[base + f1] = __float2bfloat16(v1 - __bfloat162float(b1h));
    oh[base + f2] = b2h; ol[base + f2] = __float2bfloat16(v2 - __bfloat162float(b2h));
    oh[base + f3] = b3h; ol[base + f3] = __float2bfloat16(v3 - __bfloat162float(b3h));
}

// -------- conv2 aggregation: fp32 out ---------------------------------------
__global__ void k_aggr2(const float* __restrict__ h,
                        const float* __restrict__ bias,
                        float* __restrict__ out) {
    constexpr int F = F2;
    constexpr int T = F / 4;          // 128 threads
    int i = blockIdx.x, t = threadIdx.x;
    int beg = d_rowptr[i], end = d_rowptr[i + 1];
    int f0 = t, f1 = t + T, f2 = t + 2 * T, f3 = t + 3 * T;
    int h0 = f0 >> 6, h1 = f1 >> 6, h2 = f2 >> 6, h3 = f3 >> 6;
    float a0 = 0.f, a1 = 0.f, a2 = 0.f, a3 = 0.f;
    for (int j = beg; j < end; j++) {
        int e = d_eid[j];
        int s = d_src[e];
        const float* hr = h + (size_t)s * F;
        const float* al = &d_alpha[(size_t)e * 8];
        a0 = fmaf(al[h0], hr[f0], a0);
        a1 = fmaf(al[h1], hr[f1], a1);
        a2 = fmaf(al[h2], hr[f2], a2);
        a3 = fmaf(al[h3], hr[f3], a3);
    }
    const float* iv = &d_deninv[i * 8];
    out[(size_t)i * F + f0] = eluf(a0 * iv[h0] + bias[f0]);
    out[(size_t)i * F + f1] = eluf(a1 * iv[h1] + bias[f1]);
    out[(size_t)i * F + f2] = eluf(a2 * iv[h2] + bias[f2]);
    out[(size_t)i * F + f3] = eluf(a3 * iv[h3] + bias[f3]);
}

// ---------------- mean pool over batch segments -----------------------------
__global__ void k_pool() {
    int b = blockIdx.y;
    int col = blockIdx.x * 128 + threadIdx.x;
    int beg = d_boff[b], end = d_boff[b + 1];
    float s = 0.f;
    for (int i = beg; i < end; i++) s += d_h2o[(size_t)i * F2 + col];
    float cnt = (float)(end - beg);
    d_g[b * F2 + col] = s / fmaxf(cnt, 1.0f);
}

// ---------------- FC head ----------------------------------------------------
__global__ void k_fc(const float* __restrict__ fc1w, const float* __restrict__ fc1b,
                     const float* __restrict__ fc2w, const float* __restrict__ fc2b,
                     float* __restrict__ out) {
    __shared__ float sg[16 * 32];
    int t = threadIdx.x;
    int b = t >> 5, j = t & 31;
    float s = fc1b[j];
    for (int k = 0; k < F2; k++) s = fmaf(d_g[b * F2 + k], fc1w[k * 32 + j], s);
    sg[b * 32 + j] = eluf(s);
    __syncthreads();
    if (t < 160) {
        int bb = t / 10, jj = t % 10;
        float o = fc2b[jj];
        for (int k = 0; k < 32; k++) o = fmaf(sg[bb * 32 + k], fc2w[k * 10 + jj], o);
        out[bb * 10 + jj] = o;
    }
}

// ---------------- launch -----------------------------------------------------
extern "C" void kernel_launch(void* const* d_in, const int* in_sizes, int n_in,
                              void* d_out, int out_size) {
    const float* x     = (const float*)d_in[0];
    const int*   ei    = (const int*)d_in[1];
    const int*   batch = (const int*)d_in[2];
    const float* W1    = (const float*)d_in[3];
    const float* as1   = (const float*)d_in[4];
    const float* ad1   = (const float*)d_in[5];
    const float* b1    = (const float*)d_in[6];
    const float* W2    = (const float*)d_in[7];
    const float* as2   = (const float*)d_in[8];
    const float* ad2   = (const float*)d_in[9];
    const float* b2    = (const float*)d_in[10];
    const float* f1w   = (const float*)d_in[11];
    const float* f1b   = (const float*)d_in[12];
    const float* f2w   = (const float*)d_in[13];
    const float* f2b   = (const float*)d_in[14];
    float* out = (float*)d_out;

    float *p_h1, *p_h2, *p_h2o;
    __nv_bfloat16 *p_xh, *p_xl, *p_h1oh, *p_h1ol, *p_w1th, *p_w1tl, *p_w2th, *p_w2tl;
    cudaGetSymbolAddress((void**)&p_h1,   d_h1);
    cudaGetSymbolAddress((void**)&p_h2,   d_h2);
    cudaGetSymbolAddress((void**)&p_h2o,  d_h2o);
    cudaGetSymbolAddress((void**)&p_xh,   d_xh);
    cudaGetSymbolAddress((void**)&p_xl,   d_xl);
    cudaGetSymbolAddress((void**)&p_h1oh, d_h1oh);
    cudaGetSymbolAddress((void**)&p_h1ol, d_h1ol);
    cudaGetSymbolAddress((void**)&p_w1th, d_w1th);
    cudaGetSymbolAddress((void**)&p_w1tl, d_w1tl);
    cudaGetSymbolAddress((void**)&p_w2th, d_w2th);
    cudaGetSymbolAddress((void**)&p_w2tl, d_w2tl);

    cudaFuncSetAttribute(k_gemm_mma, cudaFuncAttributeMaxDynamicSharedMemorySize,
                         GSMEM);

    // streams/events created once (first call is the uncaptured correctness run)
    static cudaStream_t sB = nullptr;
    static cudaEvent_t  eF = nullptr, eJ = nullptr;
    if (sB == nullptr) {
        cudaStreamCreateWithFlags(&sB, cudaStreamNonBlocking);
        cudaEventCreateWithFlags(&eF, cudaEventDisableTiming);
        cudaEventCreateWithFlags(&eJ, cudaEventDisableTiming);
    }

    // ---- fork: chain B (CSR + conv1 logits) || chain A (splits + GEMM1) ----
    cudaEventRecord(eF, 0);
    cudaStreamWaitEvent(sB, eF, 0);

    // chain B (stream sB)
    k_detect<<<1, 1, 0, sB>>>(ei);
    k_zero<<<(NN + 255) / 256, 256, 0, sB>>>();
    k_convhist<<<(EP + 255) / 256, 256, 0, sB>>>(ei, batch);
    k_scan<<<1, 1024, 0, sB>>>();
    k_fill<<<(EP + 255) / 256, 256, 0, sB>>>();
    k_wvec<<<8, 256, 0, sB>>>(W1, as1, ad1);
    k_attn1x<<<NN / 8, 256, 0, sB>>>(x);
    k_softmax<<<(NN * 8 + 255) / 256, 256, 0, sB>>>();

    // chain A (default stream)
    k_split<<<(NN * 128 + 255) / 256, 256>>>(x, p_xh, p_xl, NN * 128);
    k_wsplit<<<(128 * F1 + 255) / 256, 256>>>(W1, p_w1th, p_w1tl, 128, F1);
    k_wsplit<<<(F1 * F2 + 255) / 256, 256>>>(W2, p_w2th, p_w2tl, F1, F2);
    k_gemm_mma<<<dim3(F1 / 64, (NN + 127) / 128), 256, GSMEM>>>(
        p_xh, p_xl, p_w1th, p_w1tl, p_h1, NN, F1, 128);

    // ---- join ----
    cudaEventRecord(eJ, sB);
    cudaStreamWaitEvent(0, eJ, 0);

    // ---- conv1 aggregation ----
    k_aggr1<<<NN, 256>>>(p_h1, b1, p_h1oh, p_h1ol);

    // ---- conv2 ----
    k_gemm_mma<<<dim3(F2 / 64, (NN + 127) / 128), 256, GSMEM>>>(
        p_h1oh, p_h1ol, p_w2th, p_w2tl, p_h2, NN, F2, F1);
    k_attn<64><<<NN, 256>>>(p_h2, as2, ad2);
    k_softmax<<<(NN * 8 + 255) / 256, 256>>>();
    k_aggr2<<<NN, 128>>>(p_h2, b2, p_h2o);

    // ---- pool + head ----
    k_pool<<<dim3(4, BB), 128>>>();
    k_fc<<<1, 512>>>(f1w, f1b, f2w, f2b, out);
}

// round 12
// speedup vs baseline: 1.1531x; 1.1531x over previous
#include <cuda_runtime.h>
#include <cuda_bf16.h>
#include <cuda_fp16.h>
#include <math.h>
#include <stdint.h>

#define NN 10000
#define EE 160000
#define EP 170000          // edges + self loops
#define BB 16
#define F1 1024            // 8 heads * 128
#define F2 512             // 8 heads * 64

// ---------------- scratch (static device globals; no runtime alloc) ----------
__device__ __half d_h1f[(size_t)NN * F1];  // x @ W1 (fp16)
__device__ __half d_h2f[(size_t)NN * F2];  // h1o @ W2 (fp16)
__device__ float  d_h2o[(size_t)NN * F2];  // elu(conv2 out)
__device__ __nv_bfloat16 d_xh[(size_t)NN * 128];
__device__ __nv_bfloat16 d_xl[(size_t)NN * 128];
__device__ __nv_bfloat16 d_h1oh[(size_t)NN * F1];
__device__ __nv_bfloat16 d_h1ol[(size_t)NN * F1];
__device__ __nv_bfloat16 d_w1th[(size_t)F1 * 128];   // W1^T hi  [N=1024, K=128]
__device__ __nv_bfloat16 d_w1tl[(size_t)F1 * 128];
__device__ __nv_bfloat16 d_w2th[(size_t)F2 * F1];    // W2^T hi  [N=512, K=1024]
__device__ __nv_bfloat16 d_w2tl[(size_t)F2 * F1];
__device__ float d_ws1[128 * 16];          // W1 @ [a_src | a_dst]  (conv1 logits)
__device__ float d_asrc[NN * 8];
__device__ float d_adst[NN * 8];
__device__ float d_alpha[(size_t)EP * 8];  // unnormalized exp, CSR-position order
__device__ float d_deninv[NN * 8];
__device__ int   d_src[EP];
__device__ int   d_dst[EP];
__device__ int   d_ssrc[EP];               // src sorted by dst (CSR order)
__device__ int   d_batchi[NN];
__device__ int   d_is64;
__device__ int   d_cnt[NN];
__device__ int   d_rowptr[NN + 1];
__device__ int   d_cursor[NN];
__device__ int   d_bcnt[BB];
__device__ int   d_boff[BB + 1];
__device__ float d_g[BB * F2];

__device__ __forceinline__ float eluf(float x) { return x > 0.0f ? x : expm1f(x); }

// ---------------- zero + dtype probe ----------------------------------------
__global__ void k_zero(const int* __restrict__ ei_raw) {
    int t = blockIdx.x * blockDim.x + threadIdx.x;
    if (t < NN) d_cnt[t] = 0;
    if (t < BB) d_bcnt[t] = 0;
    if (t == 0) {
        int orv = 0;
#pragma unroll
        for (int i = 1; i < 16; i += 2) orv |= ei_raw[i];
        d_is64 = (orv == 0) ? 1 : 0;
    }
}

// fused: index normalization + histogram
__global__ void k_convhist(const int* __restrict__ ei_raw,
                           const int* __restrict__ batch_raw) {
    int t = blockIdx.x * blockDim.x + threadIdx.x;
    int is64 = d_is64;
    if (t < EE) {
        int s = is64 ? ei_raw[2 * t]        : ei_raw[t];
        int d = is64 ? ei_raw[2 * (EE + t)] : ei_raw[EE + t];
        d_src[t] = s; d_dst[t] = d;
        atomicAdd(&d_cnt[d], 1);
    } else if (t < EP) {
        d_src[t] = t - EE; d_dst[t] = t - EE;
        atomicAdd(&d_cnt[t - EE], 1);
    }
    if (t < NN) {
        int b = is64 ? batch_raw[2 * t] : batch_raw[t];
        d_batchi[t] = b;
        atomicAdd(&d_bcnt[b], 1);
    }
}

// warp-shuffle scan: 1024 threads, 10 elems/thread
__global__ void k_scan() {
    __shared__ int wsum[32], wpre[32];
    int t = threadIdx.x, lane = t & 31, w = t >> 5;
    int loc[10];
    int sum = 0;
#pragma unroll
    for (int j = 0; j < 10; j++) {
        int idx = t * 10 + j;
        int v = (idx < NN) ? d_cnt[idx] : 0;
        loc[j] = sum; sum += v;
    }
    int inc = sum;
#pragma unroll
    for (int off = 1; off < 32; off <<= 1) {
        int v = __shfl_up_sync(0xffffffff, inc, off);
        if (lane >= off) inc += v;
    }
    if (lane == 31) wsum[w] = inc;
    __syncthreads();
    if (w == 0) {
        int v = wsum[lane], iv = v;
#pragma unroll
        for (int off = 1; off < 32; off <<= 1) {
            int u = __shfl_up_sync(0xffffffff, iv, off);
            if (lane >= off) iv += u;
        }
        wpre[lane] = iv - v;
    }
    __syncthreads();
    int pre = wpre[w] + inc - sum;   // exclusive prefix for this thread
#pragma unroll
    for (int j = 0; j < 10; j++) {
        int idx = t * 10 + j;
        if (idx < NN) { d_rowptr[idx] = pre + loc[j]; d_cursor[idx] = pre + loc[j]; }
    }
    if (t == 1023) d_rowptr[NN] = pre + sum;
    if (t == 0) {
        d_boff[0] = 0;
        for (int b = 0; b < BB; b++) d_boff[b + 1] = d_boff[b] + d_bcnt[b];
    }
}

__global__ void k_fill() {
    int t = blockIdx.x * blockDim.x + threadIdx.x;
    if (t >= EP) return;
    int pos = atomicAdd(&d_cursor[d_dst[t]], 1);
    d_ssrc[pos] = d_src[t];
}

// ---------------- bf16 hi/lo split kernels ----------------------------------
__global__ void k_split(const float* __restrict__ a,
                        __nv_bfloat16* __restrict__ hi,
                        __nv_bfloat16* __restrict__ lo, int n) {
    int t = blockIdx.x * blockDim.x + threadIdx.x;
    if (t >= n) return;
    float v = a[t];
    __nv_bfloat16 h = __float2bfloat16(v);
    hi[t] = h;
    lo[t] = __float2bfloat16(v - __bfloat162float(h));
}

// W[K,N] -> W^T hi/lo [N,K]
__global__ void k_wsplit(const float* __restrict__ W,
                         __nv_bfloat16* __restrict__ hi,
                         __nv_bfloat16* __restrict__ lo, int K, int N) {
    int t = blockIdx.x * blockDim.x + threadIdx.x;
    if (t >= K * N) return;
    int k = t / N, n = t % N;
    float v = W[t];
    __nv_bfloat16 h = __float2bfloat16(v);
    hi[(size_t)n * K + k] = h;
    lo[(size_t)n * K + k] = __float2bfloat16(v - __bfloat162float(h));
}

// ---------------- ws1 = per-head W1 @ a_src / a_dst  -> [128, 16] ------------
__global__ void k_wvec(const float* __restrict__ W1,
                       const float* __restrict__ as1,
                       const float* __restrict__ ad1) {
    int t = blockIdx.x * blockDim.x + threadIdx.x;
    if (t >= 128 * 16) return;
    int k = t >> 4, h8 = t & 15;
    int h = h8 & 7;
    const float* a = ((h8 < 8) ? as1 : ad1) + h * 128;
    const float* w = W1 + (size_t)k * F1 + h * 128;
    float s = 0.f;
#pragma unroll 8
    for (int c = 0; c < 128; c++) s = fmaf(w[c], a[c], s);
    d_ws1[t] = s;
}

// ---------------- conv1 attention logits from x (associativity) -------------
__global__ __launch_bounds__(256) void k_attn1x(const float* __restrict__ x) {
    __shared__ float ws[128 * 17];
    int t = threadIdx.x, lane = t & 31, w = t >> 5;
    for (int v = t; v < 2048; v += 256) {
        ws[(v >> 4) * 17 + (v & 15)] = d_ws1[v];
    }
    __syncthreads();
    int i = blockIdx.x * 8 + w;
    float4 xv = ((const float4*)(x + (size_t)i * 128))[lane];
    float acc[16];
#pragma unroll
    for (int h = 0; h < 16; h++) acc[h] = 0.f;
#pragma unroll
    for (int q = 0; q < 4; q++) {
        float xq = (&xv.x)[q];
        const float* wr = &ws[(4 * lane + q) * 17];
#pragma unroll
        for (int h = 0; h < 16; h++) acc[h] = fmaf(xq, wr[h], acc[h]);
    }
#pragma unroll
    for (int off = 16; off > 0; off >>= 1)
#pragma unroll
        for (int h = 0; h < 16; h++)
            acc[h] += __shfl_xor_sync(0xffffffff, acc[h], off);
    if (lane == 0) {
#pragma unroll
        for (int h = 0; h < 8; h++) {
            d_asrc[i * 8 + h] = acc[h];
            d_adst[i * 8 + h] = acc[8 + h];
        }
    }
}

// ================= cp.async double-buffered bf16 3-term GEMM ================
// C[M,Ntot] = A @ Bt^T; fp16 output. 2 stages (3 CTAs/SM).
#define STG    30720
#define ROWB   80                 // 32 halves + 8 pad = 80B rows
#define GSMEM  (2 * STG)

__device__ __forceinline__ void cpa16(uint32_t dst, const void* src, int sz) {
    asm volatile("cp.async.cg.shared.global [%0], [%1], 16, %2;"
                 :: "r"(dst), "l"(src), "r"(sz) : "memory");
}
__device__ __forceinline__ void cpa_commit() {
    asm volatile("cp.async.commit_group;" ::: "memory");
}
template <int N>
__device__ __forceinline__ void cpa_wait() {
    asm volatile("cp.async.wait_group %0;" :: "n"(N) : "memory");
}

__device__ __forceinline__ void ldsm_x4(uint32_t& r0, uint32_t& r1,
                                        uint32_t& r2, uint32_t& r3, uint32_t a) {
    asm volatile("ldmatrix.sync.aligned.m8n8.x4.shared.b16 {%0,%1,%2,%3}, [%4];"
                 : "=r"(r0), "=r"(r1), "=r"(r2), "=r"(r3) : "r"(a));
}

__device__ __forceinline__ void mma16816(float* c, const uint32_t* a,
                                         uint32_t b0, uint32_t b1) {
    asm volatile(
        "mma.sync.aligned.m16n8k16.row.col.f32.bf16.bf16.f32 "
        "{%0,%1,%2,%3}, {%4,%5,%6,%7}, {%8,%9}, {%0,%1,%2,%3};"
        : "+f"(c[0]), "+f"(c[1]), "+f"(c[2]), "+f"(c[3])
        : "r"(a[0]), "r"(a[1]), "r"(a[2]), "r"(a[3]), "r"(b0), "r"(b1));
}

__global__ __launch_bounds__(256) void k_gemm_mma(
    const __nv_bfloat16* __restrict__ Ah, const __nv_bfloat16* __restrict__ Al,
    const __nv_bfloat16* __restrict__ Bh, const __nv_bfloat16* __restrict__ Bl,
    __half* __restrict__ C, int M, int Ntot, int K) {
    extern __shared__ char gsm[];
    uint32_t ub = (uint32_t)__cvta_generic_to_shared(gsm);
    int t = threadIdx.x, wid = t >> 5, lane = t & 31;
    int bm = blockIdx.y * 128, bn = blockIdx.x * 64;
    int wm = (wid & 3) * 32;
    int wn = (wid >> 2) * 32;

    float acc[2][4][4];
#pragma unroll
    for (int i = 0; i < 2; i++)
#pragma unroll
        for (int j = 0; j < 4; j++)
#pragma unroll
            for (int q = 0; q < 4; q++) acc[i][j][q] = 0.f;

    int g = lane >> 3, l = lane & 7;
    int arow = wm + (g & 1) * 8 + l;
    int akoff = (g >> 1) * 16;
    int brow = wn + (g >> 1) * 8 + l;
    int bkoff = (g & 1) * 16;

    int NC = K >> 5;

    int ar0 = t >> 2,         ac0 = t & 3;
    int ar1 = (t + 256) >> 2, ac1 = (t + 256) & 3;
    int br = t >> 2, bc = t & 3;

#define ISSUE(cidx, st) do {                                                  \
        uint32_t base = ub + (uint32_t)(st) * STG;                            \
        int k0 = (cidx) << 5;                                                 \
        {   int gr = bm + ar0;                                                \
            size_t gi = (((size_t)gr * K + k0) >> 3) + ac0;                   \
            int ok = (gr < M) ? 16 : 0;                                       \
            cpa16(base + ar0 * ROWB + ac0 * 16, (const uint4*)Ah + gi, ok);   \
            cpa16(base + 10240 + ar0 * ROWB + ac0 * 16, (const uint4*)Al + gi, ok); } \
        {   int gr = bm + ar1;                                                \
            size_t gi = (((size_t)gr * K + k0) >> 3) + ac1;                   \
            int ok = (gr < M) ? 16 : 0;                                       \
            cpa16(base + ar1 * ROWB + ac1 * 16, (const uint4*)Ah + gi, ok);   \
            cpa16(base + 10240 + ar1 * ROWB + ac1 * 16, (const uint4*)Al + gi, ok); } \
        {   size_t gi = (((size_t)(bn + br) * K + k0) >> 3) + bc;             \
            cpa16(base + 20480 + br * ROWB + bc * 16, (const uint4*)Bh + gi, 16); \
            cpa16(base + 25600 + br * ROWB + bc * 16, (const uint4*)Bl + gi, 16); } \
    } while (0)

    ISSUE(0, 0);
    cpa_commit();

    for (int c = 0; c < NC; c++) {
        if (c + 1 < NC) ISSUE(c + 1, (c + 1) & 1);
        cpa_commit();
        cpa_wait<1>();
        __syncthreads();

        uint32_t bA_h = ub + (uint32_t)(c & 1) * STG;
        uint32_t bA_l = bA_h + 10240;
        uint32_t bB_h = bA_h + 20480;
        uint32_t bB_l = bA_h + 25600;

#pragma unroll
        for (int ks = 0; ks < 2; ks++) {
            uint32_t ah[2][4], al[2][4], bh[2][4], bl[2][4];
#pragma unroll
            for (int mt = 0; mt < 2; mt++) {
                uint32_t off = (uint32_t)((arow + mt * 16) * ROWB + ks * 32 + akoff);
                ldsm_x4(ah[mt][0], ah[mt][1], ah[mt][2], ah[mt][3], bA_h + off);
                ldsm_x4(al[mt][0], al[mt][1], al[mt][2], al[mt][3], bA_l + off);
            }
#pragma unroll
            for (int p = 0; p < 2; p++) {
                uint32_t off = (uint32_t)((brow + p * 16) * ROWB + ks * 32 + bkoff);
                ldsm_x4(bh[p][0], bh[p][1], bh[p][2], bh[p][3], bB_h + off);
                ldsm_x4(bl[p][0], bl[p][1], bl[p][2], bl[p][3], bB_l + off);
            }
#pragma unroll
            for (int mt = 0; mt < 2; mt++)
#pragma unroll
                for (int nt = 0; nt < 4; nt++) {
                    int p = nt >> 1, q = (nt & 1) * 2;
                    mma16816(acc[mt][nt], ah[mt], bh[p][q], bh[p][q + 1]);
                    mma16816(acc[mt][nt], al[mt], bh[p][q], bh[p][q + 1]);
                    mma16816(acc[mt][nt], ah[mt], bl[p][q], bl[p][q + 1]);
                }
        }
        __syncthreads();
    }

    int erow = lane >> 2, ecol = (lane & 3) * 2;
#pragma unroll
    for (int mt = 0; mt < 2; mt++)
#pragma unroll
        for (int nt = 0; nt < 4; nt++) {
            int r0 = bm + wm + mt * 16 + erow;
            int cc = bn + wn + nt * 8 + ecol;
            if (r0 < M)
                *(__half2*)&C[(size_t)r0 * Ntot + cc] =
                    __floats2half2_rn(acc[mt][nt][0], acc[mt][nt][1]);
            int r1 = r0 + 8;
            if (r1 < M)
                *(__half2*)&C[(size_t)r1 * Ntot + cc] =
                    __floats2half2_rn(acc[mt][nt][2], acc[mt][nt][3]);
        }
#undef ISSUE
}

// ---------------- conv2 attention coefficients (reads fp16 h2) --------------
__global__ void k_attn2(const __half* __restrict__ h,
                        const float* __restrict__ a_s,
                        const float* __restrict__ a_d) {
    int i = blockIdx.x;
    int w = threadIdx.x >> 5, l = threadIdx.x & 31;
    const __half* hr = h + (size_t)i * 512 + w * 64;
    float2 f = __half22float2(*(const __half2*)&hr[2 * l]);
    float s1 = f.x * a_s[w * 64 + 2 * l] + f.y * a_s[w * 64 + 2 * l + 1];
    float s2 = f.x * a_d[w * 64 + 2 * l] + f.y * a_d[w * 64 + 2 * l + 1];
#pragma unroll
    for (int off = 16; off > 0; off >>= 1) {
        s1 += __shfl_xor_sync(0xffffffff, s1, off);
        s2 += __shfl_xor_sync(0xffffffff, s2, off);
    }
    if (l == 0) { d_asrc[i * 8 + w] = s1; d_adst[i * 8 + w] = s2; }
}

// -------- single-pass segment softmax; alpha stored in CSR position order ---
__global__ void k_softmax() {
    int t = blockIdx.x * blockDim.x + threadIdx.x;
    if (t >= NN * 8) return;
    int i = t >> 3, h = t & 7;
    int beg = d_rowptr[i], end = d_rowptr[i + 1];
    float ad = d_adst[i * 8 + h];
    float den = 0.f;
    for (int j = beg; j < end; j++) {
        int s = d_ssrc[j];
        float v = d_asrc[s * 8 + h] + ad;
        v = (v > 0.f) ? v : 0.2f * v;          // leaky_relu(0.2)
        float ex = __expf(v);
        d_alpha[(size_t)j * 8 + h] = ex;
        den += ex;
    }
    d_deninv[i * 8 + h] = 1.0f / den;
}

// -------- conv1 aggregation: gathers fp16 h1, writes bf16 hi/lo -------------
__global__ __launch_bounds__(256) void k_aggr1(const __half* __restrict__ h,
                        const float* __restrict__ bias,
                        __nv_bfloat16* __restrict__ oh,
                        __nv_bfloat16* __restrict__ ol) {
    int i = blockIdx.x, t = threadIdx.x;
    int beg = d_rowptr[i], end = d_rowptr[i + 1];
    int p0 = t, p1 = t + 256;            // half2 indices into 512-wide row
    int h0 = p0 >> 6, h1 = p1 >> 6;      // head = (2*p)/128
    float2 a0 = make_float2(0.f, 0.f), a1 = make_float2(0.f, 0.f);
    for (int j = beg; j < end; j++) {
        int s = d_ssrc[j];
        const __half2* hr = (const __half2*)(h + (size_t)s * F1);
        float al0 = d_alpha[(size_t)j * 8 + h0];
        float al1 = d_alpha[(size_t)j * 8 + h1];
        float2 v0 = __half22float2(hr[p0]);
        float2 v1 = __half22float2(hr[p1]);
        a0.x = fmaf(al0, v0.x, a0.x); a0.y = fmaf(al0, v0.y, a0.y);
        a1.x = fmaf(al1, v1.x, a1.x); a1.y = fmaf(al1, v1.y, a1.y);
    }
    const float* iv = &d_deninv[i * 8];
    float iv0 = iv[h0], iv1 = iv[h1];
    int f0 = 2 * p0, f1 = 2 * p1;
    float w0 = eluf(a0.x * iv0 + bias[f0]);
    float w1 = eluf(a0.y * iv0 + bias[f0 + 1]);
    float w2 = eluf(a1.x * iv1 + bias[f1]);
    float w3 = eluf(a1.y * iv1 + bias[f1 + 1]);
    size_t base = (size_t)i * F1;
    __nv_bfloat162 hi0 = __floats2bfloat162_rn(w0, w1);
    __nv_bfloat162 hi1 = __floats2bfloat162_rn(w2, w3);
    *(__nv_bfloat162*)&oh[base + f0] = hi0;
    *(__nv_bfloat162*)&oh[base + f1] = hi1;
    *(__nv_bfloat162*)&ol[base + f0] = __floats2bfloat162_rn(
        w0 - __bfloat162float(hi0.x), w1 - __bfloat162float(hi0.y));
    *(__nv_bfloat162*)&ol[base + f1] = __floats2bfloat162_rn(
        w2 - __bfloat162float(hi1.x), w3 - __bfloat162float(hi1.y));
}

// -------- conv2 aggregation: gathers fp16 h2, fp32 out ----------------------
__global__ __launch_bounds__(128) void k_aggr2(const __half* __restrict__ h,
                        const float* __restrict__ bias,
                        float* __restrict__ out) {
    int i = blockIdx.x, t = threadIdx.x;
    int beg = d_rowptr[i], end = d_rowptr[i + 1];
    int p0 = t, p1 = t + 128;            // half2 indices into 256-wide row
    int h0 = p0 >> 5, h1 = p1 >> 5;      // head = (2*p)/64
    float2 a0 = make_float2(0.f, 0.f), a1 = make_float2(0.f, 0.f);
    for (int j = beg; j < end; j++) {
        int s = d_ssrc[j];
        const __half2* hr = (const __half2*)(h + (size_t)s * F2);
        float al0 = d_alpha[(size_t)j * 8 + h0];
        float al1 = d_alpha[(size_t)j * 8 + h1];
        float2 v0 = __half22float2(hr[p0]);
        float2 v1 = __half22float2(hr[p1]);
        a0.x = fmaf(al0, v0.x, a0.x); a0.y = fmaf(al0, v0.y, a0.y);
        a1.x = fmaf(al1, v1.x, a1.x); a1.y = fmaf(al1, v1.y, a1.y);
    }
    const float* iv = &d_deninv[i * 8];
    float iv0 = iv[h0], iv1 = iv[h1];
    int f0 = 2 * p0, f1 = 2 * p1;
    size_t base = (size_t)i * F2;
    *(float2*)&out[base + f0] = make_float2(eluf(a0.x * iv0 + bias[f0]),
                                            eluf(a0.y * iv0 + bias[f0 + 1]));
    *(float2*)&out[base + f1] = make_float2(eluf(a1.x * iv1 + bias[f1]),
                                            eluf(a1.y * iv1 + bias[f1 + 1]));
}

// ---------------- mean pool over batch segments -----------------------------
__global__ void k_pool() {
    int b = blockIdx.y;
    int col = blockIdx.x * 128 + threadIdx.x;
    int beg = d_boff[b], end = d_boff[b + 1];
    float s = 0.f;
    for (int i = beg; i < end; i++) s += d_h2o[(size_t)i * F2 + col];
    float cnt = (float)(end - beg);
    d_g[b * F2 + col] = s / fmaxf(cnt, 1.0f);
}

// ---------------- FC head ----------------------------------------------------
__global__ void k_fc(const float* __restrict__ fc1w, const float* __restrict__ fc1b,
                     const float* __restrict__ fc2w, const float* __restrict__ fc2b,
                     float* __restrict__ out) {
    __shared__ float sg[16 * 32];
    int t = threadIdx.x;
    int b = t >> 5, j = t & 31;
    float s = fc1b[j];
    for (int k = 0; k < F2; k++) s = fmaf(d_g[b * F2 + k], fc1w[k * 32 + j], s);
    sg[b * 32 + j] = eluf(s);
    __syncthreads();
    if (t < 160) {
        int bb = t / 10, jj = t % 10;
        float o = fc2b[jj];
        for (int k = 0; k < 32; k++) o = fmaf(sg[bb * 32 + k], fc2w[k * 10 + jj], o);
        out[bb * 10 + jj] = o;
    }
}

// ---------------- launch -----------------------------------------------------
extern "C" void kernel_launch(void* const* d_in, const int* in_sizes, int n_in,
                              void* d_out, int out_size) {
    const float* x     = (const float*)d_in[0];
    const int*   ei    = (const int*)d_in[1];
    const int*   batch = (const int*)d_in[2];
    const float* W1    = (const float*)d_in[3];
    const float* as1   = (const float*)d_in[4];
    const float* ad1   = (const float*)d_in[5];
    const float* b1    = (const float*)d_in[6];
    const float* W2    = (const float*)d_in[7];
    const float* as2   = (const float*)d_in[8];
    const float* ad2   = (const float*)d_in[9];
    const float* b2    = (const float*)d_in[10];
    const float* f1w   = (const float*)d_in[11];
    const float* f1b   = (const float*)d_in[12];
    const float* f2w   = (const float*)d_in[13];
    const float* f2b   = (const float*)d_in[14];
    float* out = (float*)d_out;

    __half *p_h1f, *p_h2f;
    float *p_h2o;
    __nv_bfloat16 *p_xh, *p_xl, *p_h1oh, *p_h1ol, *p_w1th, *p_w1tl, *p_w2th, *p_w2tl;
    cudaGetSymbolAddress((void**)&p_h1f,  d_h1f);
    cudaGetSymbolAddress((void**)&p_h2f,  d_h2f);
    cudaGetSymbolAddress((void**)&p_h2o,  d_h2o);
    cudaGetSymbolAddress((void**)&p_xh,   d_xh);
    cudaGetSymbolAddress((void**)&p_xl,   d_xl);
    cudaGetSymbolAddress((void**)&p_h1oh, d_h1oh);
    cudaGetSymbolAddress((void**)&p_h1ol, d_h1ol);
    cudaGetSymbolAddress((void**)&p_w1th, d_w1th);
    cudaGetSymbolAddress((void**)&p_w1tl, d_w1tl);
    cudaGetSymbolAddress((void**)&p_w2th, d_w2th);
    cudaGetSymbolAddress((void**)&p_w2tl, d_w2tl);

    cudaFuncSetAttribute(k_gemm_mma, cudaFuncAttributeMaxDynamicSharedMemorySize,
                         GSMEM);

    // CSR + conv1 logits (independent of GEMM1)
    k_zero<<<(NN + 255) / 256, 256>>>(ei);
    k_convhist<<<(EP + 255) / 256, 256>>>(ei, batch);
    k_scan<<<1, 1024>>>();
    k_fill<<<(EP + 255) / 256, 256>>>();
    k_wvec<<<8, 256>>>(W1, as1, ad1);
    k_attn1x<<<NN / 8, 256>>>(x);
    k_softmax<<<(NN * 8 + 255) / 256, 256>>>();

    // operand prep + GEMM1 (fp16 out)
    k_split<<<(NN * 128 + 255) / 256, 256>>>(x, p_xh, p_xl, NN * 128);
    k_wsplit<<<(128 * F1 + 255) / 256, 256>>>(W1, p_w1th, p_w1tl, 128, F1);
    k_wsplit<<<(F1 * F2 + 255) / 256, 256>>>(W2, p_w2th, p_w2tl, F1, F2);
    k_gemm_mma<<<dim3(F1 / 64, (NN + 127) / 128), 256, GSMEM>>>(
        p_xh, p_xl, p_w1th, p_w1tl, p_h1f, NN, F1, 128);

    // conv1 aggregation (fp16 gather, bf16 hi/lo out)
    k_aggr1<<<NN, 256>>>(p_h1f, b1, p_h1oh, p_h1ol);

    // ---- conv2 ----
    k_gemm_mma<<<dim3(F2 / 64, (NN + 127) / 128), 256, GSMEM>>>(
        p_h1oh, p_h1ol, p_w2th, p_w2tl, p_h2f, NN, F2, F1);
    k_attn2<<<NN, 256>>>(p_h2f, as2, ad2);
    k_softmax<<<(NN * 8 + 255) / 256, 256>>>();
    k_aggr2<<<NN, 128>>>(p_h2f, b2, p_h2o);

    // ---- pool + head ----
    k_pool<<<dim3(4, BB), 128>>>();
    k_fc<<<1, 512>>>(f1w, f1b, f2w, f2b, out);
}

// round 15
// speedup vs baseline: 1.2102x; 1.0495x over previous
#include <cuda_runtime.h>
#include <cuda_bf16.h>
#include <cuda_fp16.h>
#include <math.h>
#include <stdint.h>

#define NN 10000
#define EE 160000
#define EP 170000          // edges + self loops
#define BB 16
#define F1 1024            // 8 heads * 128
#define F2 512             // 8 heads * 64

// ---------------- scratch (static device globals; no runtime alloc) ----------
__device__ __half d_h1f[(size_t)NN * F1];  // x @ W1 (fp16)
__device__ __half d_h2f[(size_t)NN * F2];  // h1o @ W2 (fp16)
__device__ float  d_h2o[(size_t)NN * F2];  // elu(conv2 out)
__device__ __nv_bfloat16 d_xh[(size_t)NN * 128];
__device__ __nv_bfloat16 d_xl[(size_t)NN * 128];
__device__ __nv_bfloat16 d_h1oh[(size_t)NN * F1];
__device__ __nv_bfloat16 d_h1ol[(size_t)NN * F1];
__device__ __nv_bfloat16 d_w1th[(size_t)F1 * 128];   // W1^T hi  [N=1024, K=128]
__device__ __nv_bfloat16 d_w1tl[(size_t)F1 * 128];
__device__ __nv_bfloat16 d_w2th[(size_t)F2 * F1];    // W2^T hi  [N=512, K=1024]
__device__ __nv_bfloat16 d_w2tl[(size_t)F2 * F1];
__device__ float d_ws1[128 * 16];          // W1 @ [a_src | a_dst]  (conv1 logits)
__device__ float d_asrc[NN * 8];
__device__ float d_adst[NN * 8];
__device__ float d_alpha[(size_t)EP * 8];  // unnormalized exp, CSR-position order
__device__ float d_deninv[NN * 8];
__device__ int   d_src[EP];
__device__ int   d_dst[EP];
__device__ int   d_ssrc[EP];               // src sorted by dst (CSR order)
__device__ int   d_batchi[NN];
__device__ int   d_is64;
__device__ int   d_cnt[NN];
__device__ int   d_rowptr[NN + 1];
__device__ int   d_cursor[NN];
__device__ int   d_bcnt[BB];
__device__ int   d_boff[BB + 1];
__device__ float d_g[BB * F2];

__device__ __forceinline__ float eluf(float x) { return x > 0.0f ? x : expm1f(x); }

// ---------------- zero + dtype probe ----------------------------------------
__global__ void k_zero(const int* __restrict__ ei_raw) {
    int t = blockIdx.x * blockDim.x + threadIdx.x;
    if (t < NN) d_cnt[t] = 0;
    if (t < BB) d_bcnt[t] = 0;
    if (t == 0) {
        int orv = 0;
#pragma unroll
        for (int i = 1; i < 16; i += 2) orv |= ei_raw[i];
        d_is64 = (orv == 0) ? 1 : 0;
    }
}

// fused: index normalization + histogram
__global__ void k_convhist(const int* __restrict__ ei_raw,
                           const int* __restrict__ batch_raw) {
    int t = blockIdx.x * blockDim.x + threadIdx.x;
    int is64 = d_is64;
    if (t < EE) {
        int s = is64 ? ei_raw[2 * t]        : ei_raw[t];
        int d = is64 ? ei_raw[2 * (EE + t)] : ei_raw[EE + t];
        d_src[t] = s; d_dst[t] = d;
        atomicAdd(&d_cnt[d], 1);
    } else if (t < EP) {
        d_src[t] = t - EE; d_dst[t] = t - EE;
        atomicAdd(&d_cnt[t - EE], 1);
    }
    if (t < NN) {
        int b = is64 ? batch_raw[2 * t] : batch_raw[t];
        d_batchi[t] = b;
        atomicAdd(&d_bcnt[b], 1);
    }
}

// warp-shuffle scan: 1024 threads, 10 elems/thread
__global__ void k_scan() {
    __shared__ int wsum[32], wpre[32];
    int t = threadIdx.x, lane = t & 31, w = t >> 5;
    int loc[10];
    int sum = 0;
#pragma unroll
    for (int j = 0; j < 10; j++) {
        int idx = t * 10 + j;
        int v = (idx < NN) ? d_cnt[idx] : 0;
        loc[j] = sum; sum += v;
    }
    int inc = sum;
#pragma unroll
    for (int off = 1; off < 32; off <<= 1) {
        int v = __shfl_up_sync(0xffffffff, inc, off);
        if (lane >= off) inc += v;
    }
    if (lane == 31) wsum[w] = inc;
    __syncthreads();
    if (w == 0) {
        int v = wsum[lane], iv = v;
#pragma unroll
        for (int off = 1; off < 32; off <<= 1) {
            int u = __shfl_up_sync(0xffffffff, iv, off);
            if (lane >= off) iv += u;
        }
        wpre[lane] = iv - v;
    }
    __syncthreads();
    int pre = wpre[w] + inc - sum;   // exclusive prefix for this thread
#pragma unroll
    for (int j = 0; j < 10; j++) {
        int idx = t * 10 + j;
        if (idx < NN) { d_rowptr[idx] = pre + loc[j]; d_cursor[idx] = pre + loc[j]; }
    }
    if (t == 1023) d_rowptr[NN] = pre + sum;
    if (t == 0) {
        d_boff[0] = 0;
        for (int b = 0; b < BB; b++) d_boff[b + 1] = d_boff[b] + d_bcnt[b];
    }
}

__global__ void k_fill() {
    int t = blockIdx.x * blockDim.x + threadIdx.x;
    if (t >= EP) return;
    int pos = atomicAdd(&d_cursor[d_dst[t]], 1);
    d_ssrc[pos] = d_src[t];
}

// ---------------- bf16 hi/lo split kernels ----------------------------------
__global__ void k_split(const float* __restrict__ a,
                        __nv_bfloat16* __restrict__ hi,
                        __nv_bfloat16* __restrict__ lo, int n) {
    int t = blockIdx.x * blockDim.x + threadIdx.x;
    if (t >= n) return;
    float v = a[t];
    __nv_bfloat16 h = __float2bfloat16(v);
    hi[t] = h;
    lo[t] = __float2bfloat16(v - __bfloat162float(h));
}

// W[K,N] -> W^T hi/lo [N,K]
__global__ void k_wsplit(const float* __restrict__ W,
                         __nv_bfloat16* __restrict__ hi,
                         __nv_bfloat16* __restrict__ lo, int K, int N) {
    int t = blockIdx.x * blockDim.x + threadIdx.x;
    if (t >= K * N) return;
    int k = t / N, n = t % N;
    float v = W[t];
    __nv_bfloat16 h = __float2bfloat16(v);
    hi[(size_t)n * K + k] = h;
    lo[(size_t)n * K + k] = __float2bfloat16(v - __bfloat162float(h));
}

// ---------------- ws1 = per-head W1 @ a_src / a_dst  -> [128, 16] ------------
__global__ void k_wvec(const float* __restrict__ W1,
                       const float* __restrict__ as1,
                       const float* __restrict__ ad1) {
    int t = blockIdx.x * blockDim.x + threadIdx.x;
    if (t >= 128 * 16) return;
    int k = t >> 4, h8 = t & 15;
    int h = h8 & 7;
    const float* a = ((h8 < 8) ? as1 : ad1) + h * 128;
    const float* w = W1 + (size_t)k * F1 + h * 128;
    float s = 0.f;
#pragma unroll 8
    for (int c = 0; c < 128; c++) s = fmaf(w[c], a[c], s);
    d_ws1[t] = s;
}

// ---------------- conv1 attention logits from x (associativity) -------------
__global__ __launch_bounds__(256) void k_attn1x(const float* __restrict__ x) {
    __shared__ float ws[128 * 17];
    int t = threadIdx.x, lane = t & 31, w = t >> 5;
    for (int v = t; v < 2048; v += 256) {
        ws[(v >> 4) * 17 + (v & 15)] = d_ws1[v];
    }
    __syncthreads();
    int i = blockIdx.x * 8 + w;
    float4 xv = ((const float4*)(x + (size_t)i * 128))[lane];
    float acc[16];
#pragma unroll
    for (int h = 0; h < 16; h++) acc[h] = 0.f;
#pragma unroll
    for (int q = 0; q < 4; q++) {
        float xq = (&xv.x)[q];
        const float* wr = &ws[(4 * lane + q) * 17];
#pragma unroll
        for (int h = 0; h < 16; h++) acc[h] = fmaf(xq, wr[h], acc[h]);
    }
#pragma unroll
    for (int off = 16; off > 0; off >>= 1)
#pragma unroll
        for (int h = 0; h < 16; h++)
            acc[h] += __shfl_xor_sync(0xffffffff, acc[h], off);
    if (lane == 0) {
#pragma unroll
        for (int h = 0; h < 8; h++) {
            d_asrc[i * 8 + h] = acc[h];
            d_adst[i * 8 + h] = acc[8 + h];
        }
    }
}

// ================= cp.async double-buffered bf16 3-term GEMM ================
// C[M,Ntot] = A @ Bt^T; fp16 output. 2 stages (3 CTAs/SM).
#define STG    30720
#define ROWB   80                 // 32 halves + 8 pad = 80B rows
#define GSMEM  (2 * STG)

__device__ __forceinline__ void cpa16(uint32_t dst, const void* src, int sz) {
    asm volatile("cp.async.cg.shared.global [%0], [%1], 16, %2;"
                 :: "r"(dst), "l"(src), "r"(sz) : "memory");
}
__device__ __forceinline__ void cpa_commit() {
    asm volatile("cp.async.commit_group;" ::: "memory");
}
template <int N>
__device__ __forceinline__ void cpa_wait() {
    asm volatile("cp.async.wait_group %0;" :: "n"(N) : "memory");
}

__device__ __forceinline__ void ldsm_x4(uint32_t& r0, uint32_t& r1,
                                        uint32_t& r2, uint32_t& r3, uint32_t a) {
    asm volatile("ldmatrix.sync.aligned.m8n8.x4.shared.b16 {%0,%1,%2,%3}, [%4];"
                 : "=r"(r0), "=r"(r1), "=r"(r2), "=r"(r3) : "r"(a));
}

__device__ __forceinline__ void mma16816(float* c, const uint32_t* a,
                                         uint32_t b0, uint32_t b1) {
    asm volatile(
        "mma.sync.aligned.m16n8k16.row.col.f32.bf16.bf16.f32 "
        "{%0,%1,%2,%3}, {%4,%5,%6,%7}, {%8,%9}, {%0,%1,%2,%3};"
        : "+f"(c[0]), "+f"(c[1]), "+f"(c[2]), "+f"(c[3])
        : "r"(a[0]), "r"(a[1]), "r"(a[2]), "r"(a[3]), "r"(b0), "r"(b1));
}

__global__ __launch_bounds__(256) void k_gemm_mma(
    const __nv_bfloat16* __restrict__ Ah, const __nv_bfloat16* __restrict__ Al,
    const __nv_bfloat16* __restrict__ Bh, const __nv_bfloat16* __restrict__ Bl,
    __half* __restrict__ C, int M, int Ntot, int K) {
    extern __shared__ char gsm[];
    uint32_t ub = (uint32_t)__cvta_generic_to_shared(gsm);
    int t = threadIdx.x, wid = t >> 5, lane = t & 31;
    int bm = blockIdx.y * 128, bn = blockIdx.x * 64;
    int wm = (wid & 3) * 32;
    int wn = (wid >> 2) * 32;

    float acc[2][4][4];
#pragma unroll
    for (int i = 0; i < 2; i++)
#pragma unroll
        for (int j = 0; j < 4; j++)
#pragma unroll
            for (int q = 0; q < 4; q++) acc[i][j][q] = 0.f;

    int g = lane >> 3, l = lane & 7;
    int arow = wm + (g & 1) * 8 + l;
    int akoff = (g >> 1) * 16;
    int brow = wn + (g >> 1) * 8 + l;
    int bkoff = (g & 1) * 16;

    int NC = K >> 5;

    int ar0 = t >> 2,         ac0 = t & 3;
    int ar1 = (t + 256) >> 2, ac1 = (t + 256) & 3;
    int br = t >> 2, bc = t & 3;

#define ISSUE(cidx, st) do {                                                  \
        uint32_t base = ub + (uint32_t)(st) * STG;                            \
        int k0 = (cidx) << 5;                                                 \
        {   int gr = bm + ar0;                                                \
            size_t gi = (((size_t)gr * K + k0) >> 3) + ac0;                   \
            int ok = (gr < M) ? 16 : 0;                                       \
            cpa16(base + ar0 * ROWB + ac0 * 16, (const uint4*)Ah + gi, ok);   \
            cpa16(base + 10240 + ar0 * ROWB + ac0 * 16, (const uint4*)Al + gi, ok); } \
        {   int gr = bm + ar1;                                                \
            size_t gi = (((size_t)gr * K + k0) >> 3) + ac1;                   \
            int ok = (gr < M) ? 16 : 0;                                       \
            cpa16(base + ar1 * ROWB + ac1 * 16, (const uint4*)Ah + gi, ok);   \
            cpa16(base + 10240 + ar1 * ROWB + ac1 * 16, (const uint4*)Al + gi, ok); } \
        {   size_t gi = (((size_t)(bn + br) * K + k0) >> 3) + bc;             \
            cpa16(base + 20480 + br * ROWB + bc * 16, (const uint4*)Bh + gi, 16); \
            cpa16(base + 25600 + br * ROWB + bc * 16, (const uint4*)Bl + gi, 16); } \
    } while (0)

    ISSUE(0, 0);
    cpa_commit();

    for (int c = 0; c < NC; c++) {
        if (c + 1 < NC) ISSUE(c + 1, (c + 1) & 1);
        cpa_commit();
        cpa_wait<1>();
        __syncthreads();

        uint32_t bA_h = ub + (uint32_t)(c & 1) * STG;
        uint32_t bA_l = bA_h + 10240;
        uint32_t bB_h = bA_h + 20480;
        uint32_t bB_l = bA_h + 25600;

#pragma unroll
        for (int ks = 0; ks < 2; ks++) {
            uint32_t ah[2][4], al[2][4], bh[2][4], bl[2][4];
#pragma unroll
            for (int mt = 0; mt < 2; mt++) {
                uint32_t off = (uint32_t)((arow + mt * 16) * ROWB + ks * 32 + akoff);
                ldsm_x4(ah[mt][0], ah[mt][1], ah[mt][2], ah[mt][3], bA_h + off);
                ldsm_x4(al[mt][0], al[mt][1], al[mt][2], al[mt][3], bA_l + off);
            }
#pragma unroll
            for (int p = 0; p < 2; p++) {
                uint32_t off = (uint32_t)((brow + p * 16) * ROWB + ks * 32 + bkoff);
                ldsm_x4(bh[p][0], bh[p][1], bh[p][2], bh[p][3], bB_h + off);
                ldsm_x4(bl[p][0], bl[p][1], bl[p][2], bl[p][3], bB_l + off);
            }
#pragma unroll
            for (int mt = 0; mt < 2; mt++)
#pragma unroll
                for (int nt = 0; nt < 4; nt++) {
                    int p = nt >> 1, q = (nt & 1) * 2;
                    mma16816(acc[mt][nt], ah[mt], bh[p][q], bh[p][q + 1]);
                    mma16816(acc[mt][nt], al[mt], bh[p][q], bh[p][q + 1]);
                    mma16816(acc[mt][nt], ah[mt], bl[p][q], bl[p][q + 1]);
                }
        }
        __syncthreads();
    }

    int erow = lane >> 2, ecol = (lane & 3) * 2;
#pragma unroll
    for (int mt = 0; mt < 2; mt++)
#pragma unroll
        for (int nt = 0; nt < 4; nt++) {
            int r0 = bm + wm + mt * 16 + erow;
            int cc = bn + wn + nt * 8 + ecol;
            if (r0 < M)
                *(__half2*)&C[(size_t)r0 * Ntot + cc] =
                    __floats2half2_rn(acc[mt][nt][0], acc[mt][nt][1]);
            int r1 = r0 + 8;
            if (r1 < M)
                *(__half2*)&C[(size_t)r1 * Ntot + cc] =
                    __floats2half2_rn(acc[mt][nt][2], acc[mt][nt][3]);
        }
#undef ISSUE
}

// ---------------- conv2 attention coefficients (reads fp16 h2) --------------
__global__ void k_attn2(const __half* __restrict__ h,
                        const float* __restrict__ a_s,
                        const float* __restrict__ a_d) {
    int i = blockIdx.x;
    int w = threadIdx.x >> 5, l = threadIdx.x & 31;
    const __half* hr = h + (size_t)i * 512 + w * 64;
    float2 f = __half22float2(*(const __half2*)&hr[2 * l]);
    float s1 = f.x * a_s[w * 64 + 2 * l] + f.y * a_s[w * 64 + 2 * l + 1];
    float s2 = f.x * a_d[w * 64 + 2 * l] + f.y * a_d[w * 64 + 2 * l + 1];
#pragma unroll
    for (int off = 16; off > 0; off >>= 1) {
        s1 += __shfl_xor_sync(0xffffffff, s1, off);
        s2 += __shfl_xor_sync(0xffffffff, s2, off);
    }
    if (l == 0) { d_asrc[i * 8 + w] = s1; d_adst[i * 8 + w] = s2; }
}

// -------- single-pass segment softmax; alpha stored in CSR position order ---
__global__ void k_softmax() {
    int t = blockIdx.x * blockDim.x + threadIdx.x;
    if (t >= NN * 8) return;
    int i = t >> 3, h = t & 7;
    int beg = d_rowptr[i], end = d_rowptr[i + 1];
    float ad = d_adst[i * 8 + h];
    float den = 0.f;
    for (int j = beg; j < end; j++) {
        int s = d_ssrc[j];
        float v = d_asrc[s * 8 + h] + ad;
        v = (v > 0.f) ? v : 0.2f * v;          // leaky_relu(0.2)
        float ex = __expf(v);
        d_alpha[(size_t)j * 8 + h] = ex;
        den += ex;
    }
    d_deninv[i * 8 + h] = 1.0f / den;
}

// -------- conv1 aggregation: gathers fp16 h1, writes bf16 hi/lo -------------
__global__ __launch_bounds__(256) void k_aggr1(const __half* __restrict__ h,
                        const float* __restrict__ bias,
                        __nv_bfloat16* __restrict__ oh,
                        __nv_bfloat16* __restrict__ ol) {
    int i = blockIdx.x, t = threadIdx.x;
    int beg = d_rowptr[i], end = d_rowptr[i + 1];
    int p0 = t, p1 = t + 256;            // half2 indices into 512-wide row
    int h0 = p0 >> 6, h1 = p1 >> 6;      // head = (2*p)/128
    float2 a0 = make_float2(0.f, 0.f), a1 = make_float2(0.f, 0.f);
    for (int j = beg; j < end; j++) {
        int s = d_ssrc[j];
        const __half2* hr = (const __half2*)(h + (size_t)s * F1);
        float al0 = d_alpha[(size_t)j * 8 + h0];
        float al1 = d_alpha[(size_t)j * 8 + h1];
        float2 v0 = __half22float2(hr[p0]);
        float2 v1 = __half22float2(hr[p1]);
        a0.x = fmaf(al0, v0.x, a0.x); a0.y = fmaf(al0, v0.y, a0.y);
        a1.x = fmaf(al1, v1.x, a1.x); a1.y = fmaf(al1, v1.y, a1.y);
    }
    const float* iv = &d_deninv[i * 8];
    float iv0 = iv[h0], iv1 = iv[h1];
    int f0 = 2 * p0, f1 = 2 * p1;
    float w0 = eluf(a0.x * iv0 + bias[f0]);
    float w1 = eluf(a0.y * iv0 + bias[f0 + 1]);
    float w2 = eluf(a1.x * iv1 + bias[f1]);
    float w3 = eluf(a1.y * iv1 + bias[f1 + 1]);
    size_t base = (size_t)i * F1;
    __nv_bfloat162 hi0 = __floats2bfloat162_rn(w0, w1);
    __nv_bfloat162 hi1 = __floats2bfloat162_rn(w2, w3);
    *(__nv_bfloat162*)&oh[base + f0] = hi0;
    *(__nv_bfloat162*)&oh[base + f1] = hi1;
    *(__nv_bfloat162*)&ol[base + f0] = __floats2bfloat162_rn(
        w0 - __bfloat162float(hi0.x), w1 - __bfloat162float(hi0.y));
    *(__nv_bfloat162*)&ol[base + f1] = __floats2bfloat162_rn(
        w2 - __bfloat162float(hi1.x), w3 - __bfloat162float(hi1.y));
}

// -------- conv2 aggregation: gathers fp16 h2, fp32 out ----------------------
__global__ __launch_bounds__(128) void k_aggr2(const __half* __restrict__ h,
                        const float* __restrict__ bias,
                        float* __restrict__ out) {
    int i = blockIdx.x, t = threadIdx.x;
    int beg = d_rowptr[i], end = d_rowptr[i + 1];
    int p0 = t, p1 = t + 128;            // half2 indices into 256-wide row
    int h0 = p0 >> 5, h1 = p1 >> 5;      // head = (2*p)/64
    float2 a0 = make_float2(0.f, 0.f), a1 = make_float2(0.f, 0.f);
    for (int j = beg; j < end; j++) {
        int s = d_ssrc[j];
        const __half2* hr = (const __half2*)(h + (size_t)s * F2);
        float al0 = d_alpha[(size_t)j * 8 + h0];
        float al1 = d_alpha[(size_t)j * 8 + h1];
        float2 v0 = __half22float2(hr[p0]);
        float2 v1 = __half22float2(hr[p1]);
        a0.x = fmaf(al0, v0.x, a0.x); a0.y = fmaf(al0, v0.y, a0.y);
        a1.x = fmaf(al1, v1.x, a1.x); a1.y = fmaf(al1, v1.y, a1.y);
    }
    const float* iv = &d_deninv[i * 8];
    float iv0 = iv[h0], iv1 = iv[h1];
    int f0 = 2 * p0, f1 = 2 * p1;
    size_t base = (size_t)i * F2;
    *(float2*)&out[base + f0] = make_float2(eluf(a0.x * iv0 + bias[f0]),
                                            eluf(a0.y * iv0 + bias[f0 + 1]));
    *(float2*)&out[base + f1] = make_float2(eluf(a1.x * iv1 + bias[f1]),
                                            eluf(a1.y * iv1 + bias[f1 + 1]));
}

// ---------------- mean pool over batch segments -----------------------------
__global__ void k_pool() {
    int b = blockIdx.y;
    int col = blockIdx.x * 128 + threadIdx.x;
    int beg = d_boff[b], end = d_boff[b + 1];
    float s = 0.f;
    for (int i = beg; i < end; i++) s += d_h2o[(size_t)i * F2 + col];
    float cnt = (float)(end - beg);
    d_g[b * F2 + col] = s / fmaxf(cnt, 1.0f);
}

// ---------------- FC head ----------------------------------------------------
__global__ void k_fc(const float* __restrict__ fc1w, const float* __restrict__ fc1b,
                     const float* __restrict__ fc2w, const float* __restrict__ fc2b,
                     float* __restrict__ out) {
    __shared__ float sg[16 * 32];
    int t = threadIdx.x;
    int b = t >> 5, j = t & 31;
    float s = fc1b[j];
    for (int k = 0; k < F2; k++) s = fmaf(d_g[b * F2 + k], fc1w[k * 32 + j], s);
    sg[b * 32 + j] = eluf(s);
    __syncthreads();
    if (t < 160) {
        int bb = t / 10, jj = t % 10;
        float o = fc2b[jj];
        for (int k = 0; k < 32; k++) o = fmaf(sg[bb * 32 + k], fc2w[k * 10 + jj], o);
        out[bb * 10 + jj] = o;
    }
}

// ---------------- launch -----------------------------------------------------
extern "C" void kernel_launch(void* const* d_in, const int* in_sizes, int n_in,
                              void* d_out, int out_size) {
    const float* x     = (const float*)d_in[0];
    const int*   ei    = (const int*)d_in[1];
    const int*   batch = (const int*)d_in[2];
    const float* W1    = (const float*)d_in[3];
    const float* as1   = (const float*)d_in[4];
    const float* ad1   = (const float*)d_in[5];
    const float* b1    = (const float*)d_in[6];
    const float* W2    = (const float*)d_in[7];
    const float* as2   = (const float*)d_in[8];
    const float* ad2   = (const float*)d_in[9];
    const float* b2    = (const float*)d_in[10];
    const float* f1w   = (const float*)d_in[11];
    const float* f1b   = (const float*)d_in[12];
    const float* f2w   = (const float*)d_in[13];
    const float* f2b   = (const float*)d_in[14];
    float* out = (float*)d_out;

    __half *p_h1f, *p_h2f;
    float *p_h2o;
    __nv_bfloat16 *p_xh, *p_xl, *p_h1oh, *p_h1ol, *p_w1th, *p_w1tl, *p_w2th, *p_w2tl;
    cudaGetSymbolAddress((void**)&p_h1f,  d_h1f);
    cudaGetSymbolAddress((void**)&p_h2f,  d_h2f);
    cudaGetSymbolAddress((void**)&p_h2o,  d_h2o);
    cudaGetSymbolAddress((void**)&p_xh,   d_xh);
    cudaGetSymbolAddress((void**)&p_xl,   d_xl);
    cudaGetSymbolAddress((void**)&p_h1oh, d_h1oh);
    cudaGetSymbolAddress((void**)&p_h1ol, d_h1ol);
    cudaGetSymbolAddress((void**)&p_w1th, d_w1th);
    cudaGetSymbolAddress((void**)&p_w1tl, d_w1tl);
    cudaGetSymbolAddress((void**)&p_w2th, d_w2th);
    cudaGetSymbolAddress((void**)&p_w2tl, d_w2tl);

    cudaFuncSetAttribute(k_gemm_mma, cudaFuncAttributeMaxDynamicSharedMemorySize,
                         GSMEM);

    // streams/events created once (first call is the uncaptured correctness run)
    static cudaStream_t sB = nullptr;
    static cudaEvent_t  eF = nullptr, eJ = nullptr;
    if (sB == nullptr) {
        cudaStreamCreateWithFlags(&sB, cudaStreamNonBlocking);
        cudaEventCreateWithFlags(&eF, cudaEventDisableTiming);
        cudaEventCreateWithFlags(&eJ, cudaEventDisableTiming);
    }

    // ---- fork: chain B (CSR + conv1 logits + softmax1) || chain A ----------
    cudaEventRecord(eF, 0);
    cudaStreamWaitEvent(sB, eF, 0);

    // chain B (stream sB) — latency-bound serial prefix
    k_zero<<<(NN + 255) / 256, 256, 0, sB>>>(ei);
    k_convhist<<<(EP + 255) / 256, 256, 0, sB>>>(ei, batch);
    k_scan<<<1, 1024, 0, sB>>>();
    k_fill<<<(EP + 255) / 256, 256, 0, sB>>>();
    k_wvec<<<8, 256, 0, sB>>>(W1, as1, ad1);
    k_attn1x<<<NN / 8, 256, 0, sB>>>(x);
    k_softmax<<<(NN * 8 + 255) / 256, 256, 0, sB>>>();

    // chain A (default stream) — throughput work
    k_split<<<(NN * 128 + 255) / 256, 256>>>(x, p_xh, p_xl, NN * 128);
    k_wsplit<<<(128 * F1 + 255) / 256, 256>>>(W1, p_w1th, p_w1tl, 128, F1);
    k_wsplit<<<(F1 * F2 + 255) / 256, 256>>>(W2, p_w2th, p_w2tl, F1, F2);
    k_gemm_mma<<<dim3(F1 / 64, (NN + 127) / 128), 256, GSMEM>>>(
        p_xh, p_xl, p_w1th, p_w1tl, p_h1f, NN, F1, 128);

    // ---- join ----
    cudaEventRecord(eJ, sB);
    cudaStreamWaitEvent(0, eJ, 0);

    // conv1 aggregation (fp16 gather, bf16 hi/lo out)
    k_aggr1<<<NN, 256>>>(p_h1f, b1, p_h1oh, p_h1ol);

    // ---- conv2 ----
    k_gemm_mma<<<dim3(F2 / 64, (NN + 127) / 128), 256, GSMEM>>>(
        p_h1oh, p_h1ol, p_w2th, p_w2tl, p_h2f, NN, F2, F1);
    k_attn2<<<NN, 256>>>(p_h2f, as2, ad2);
    k_softmax<<<(NN * 8 + 255) / 256, 256>>>();
    k_aggr2<<<NN, 128>>>(p_h2f, b2, p_h2o);

    // ---- pool + head ----
    k_pool<<<dim3(4, BB), 128>>>();
    k_fc<<<1, 512>>>(f1w, f1b, f2w, f2b, out);
}